// round 5
// baseline (speedup 1.0000x reference)
#include <cuda_runtime.h>
#include <cstdint>
#include <cmath>

#define BB   256
#define TT   1024
#define OBS  64
#define NN   512
#define AA   8
#define BETA 0.9f
#define V_TH 1.0f

// Scratch: __device__ globals (runtime allocation is forbidden)
__device__ float g_WT[NN * NN];              // W_T[j][i] = W_rec[i][j]
__device__ float g_WoutT[NN * AA];           // [i][a]
__device__ float g_I[(size_t)BB * TT * NN];  // x @ W_in^T, precomputed

// ---------- prep: transposes ----------
__global__ void prep_kernel(const float* __restrict__ Wrec,
                            const float* __restrict__ Wout)
{
    int idx = blockIdx.x * 256 + threadIdx.x;
    if (idx < NN * NN) {
        int i = idx >> 9, j = idx & (NN - 1);
        g_WT[j * NN + i] = Wrec[idx];
    }
    if (idx < NN * AA) {
        int a = idx >> 9, i = idx & (NN - 1);
        g_WoutT[i * AA + a] = Wout[idx];
    }
}

// ---------- input GEMM: g_I[r,i] = sum_k X[r,k] * Win[i,k] ----------
// Single sequential-k fma chain per output element (k = 0..63 strictly increasing)
// to match a cuBLAS-style single-accumulator k-loop bitwise.
__global__ void __launch_bounds__(256, 2) ingemm_kernel(const float* __restrict__ X,
                                                        const float* __restrict__ Win)
{
    __shared__ float As[128][OBS];  // 32KB
    __shared__ float Bs[OBS][64];   // 16KB
    const int row0 = blockIdx.x * 128;
    const int col0 = blockIdx.y * 64;
    const int tid  = threadIdx.x;

    #pragma unroll
    for (int l = tid; l < 128 * 16; l += 256) {
        int r = l >> 4, kq = l & 15;
        float4 v = reinterpret_cast<const float4*>(X + (size_t)(row0 + r) * OBS)[kq];
        *reinterpret_cast<float4*>(&As[r][kq * 4]) = v;
    }
    #pragma unroll
    for (int l = tid; l < 64 * 16; l += 256) {
        int i = l & 63, kq = l >> 6;
        float4 v = reinterpret_cast<const float4*>(Win + (size_t)(col0 + i) * OBS)[kq];
        Bs[kq * 4 + 0][i] = v.x;
        Bs[kq * 4 + 1][i] = v.y;
        Bs[kq * 4 + 2][i] = v.z;
        Bs[kq * 4 + 3][i] = v.w;
    }
    __syncthreads();

    const int tx = tid & 15, ty = tid >> 4;
    float acc[8][4];
    #pragma unroll
    for (int u = 0; u < 8; u++)
        #pragma unroll
        for (int c = 0; c < 4; c++) acc[u][c] = 0.f;

    #pragma unroll 8
    for (int k = 0; k < OBS; k++) {
        float4 b4 = *reinterpret_cast<const float4*>(&Bs[k][tx * 4]);
        #pragma unroll
        for (int u = 0; u < 8; u++) {
            float a = As[ty * 8 + u][k];
            acc[u][0] = __fmaf_rn(a, b4.x, acc[u][0]);
            acc[u][1] = __fmaf_rn(a, b4.y, acc[u][1]);
            acc[u][2] = __fmaf_rn(a, b4.z, acc[u][2]);
            acc[u][3] = __fmaf_rn(a, b4.w, acc[u][3]);
        }
    }
    #pragma unroll
    for (int u = 0; u < 8; u++) {
        size_t r = (size_t)(row0 + ty * 8 + u);
        float4 st = make_float4(acc[u][0], acc[u][1], acc[u][2], acc[u][3]);
        *reinterpret_cast<float4*>(&g_I[r * NN + col0 + tx * 4]) = st;
    }
}

// ---------- persistent LIF scan: one block per batch row ----------
// Bitwise-ordered state update:
//   R  = sum over spiking j (increasing j) of W_rec[i,j], individual __fadd_rn
//   v' = (fma(BETA, v, R) + I) - s      (LLVM/XLA contraction of BETA*v + R)
__global__ void __launch_bounds__(512, 2) lif_kernel(float* __restrict__ out)
{
    const int b = blockIdx.x, i = threadIdx.x;
    const int warp = i >> 5, lane = i & 31;

    __shared__ int   s_cnt[2][16];
    __shared__ short s_list[2][512];
    __shared__ float s_part[2][16 * AA];

    float wo[AA];
    #pragma unroll
    for (int a = 0; a < AA; a++) wo[a] = g_WoutT[i * AA + a];

    float v = 0.f;
    bool  sp = false;
    if (lane == 0) s_cnt[0][warp] = 0;
    __syncthreads();

    const float* Irow = g_I + (size_t)b * TT * NN + i;
    float*       orow = out + (size_t)b * TT * AA;

    for (int t = 0; t < TT; t++) {
        const int par = t & 1;

        // finalize previous step's 8 outputs (output path: no feedback, any order OK)
        if (t > 0 && i < AA) {
            float s = 0.f;
            #pragma unroll
            for (int w = 0; w < 16; w++) s += s_part[par ^ 1][w * AA + i];
            orow[(size_t)(t - 1) * AA + i] = (float)tanh((double)s);
        }

        // sparse recurrent gather: strict sequential adds in increasing j
        float R = 0.f;
        #pragma unroll 1
        for (int w = 0; w < 16; w++) {
            const int n = s_cnt[par][w];
            const short* lst = &s_list[par][w << 5];
            int l = 0;
            for (; l + 4 <= n; l += 4) {
                float w0 = g_WT[lst[l]     * NN + i];
                float w1 = g_WT[lst[l + 1] * NN + i];
                float w2 = g_WT[lst[l + 2] * NN + i];
                float w3 = g_WT[lst[l + 3] * NN + i];
                R = __fadd_rn(R, w0);
                R = __fadd_rn(R, w1);
                R = __fadd_rn(R, w2);
                R = __fadd_rn(R, w3);
            }
            for (; l < n; l++) R = __fadd_rn(R, g_WT[lst[l] * NN + i]);
        }

        // v' = (fma(BETA,v,R) + I) - V_TH*s
        float acc = __fmaf_rn(BETA, v, R);
        acc = __fadd_rn(acc, __ldg(Irow + (size_t)t * NN));
        if (sp) acc = __fadd_rn(acc, -V_TH);
        v  = acc;
        sp = v > V_TH;

        // output partials: warp shuffle reduce of v*wo[a]
        float p[AA];
        #pragma unroll
        for (int a = 0; a < AA; a++) {
            p[a] = v * wo[a];
            #pragma unroll
            for (int off = 16; off > 0; off >>= 1)
                p[a] += __shfl_down_sync(0xffffffffu, p[a], off);
        }
        if (lane == 0) {
            #pragma unroll
            for (int a = 0; a < AA; a++) s_part[par][warp * AA + a] = p[a];
        }

        // build next step's spike list (ballot compaction, order-preserving)
        unsigned m = __ballot_sync(0xffffffffu, sp);
        if (lane == 0) s_cnt[par ^ 1][warp] = __popc(m);
        if (sp) s_list[par ^ 1][(warp << 5) + __popc(m & ((1u << lane) - 1u))] = (short)i;

        __syncthreads();
    }

    // finalize last step's outputs
    if (i < AA) {
        float s = 0.f;
        #pragma unroll
        for (int w = 0; w < 16; w++) s += s_part[(TT - 1) & 1][w * AA + i];
        orow[(size_t)(TT - 1) * AA + i] = (float)tanh((double)s);
    }
}

extern "C" void kernel_launch(void* const* d_in, const int* in_sizes, int n_in,
                              void* d_out, int out_size)
{
    const float* X    = (const float*)d_in[0];  // [B,T,OBS]
    const float* Wrec = (const float*)d_in[1];  // [N,N]
    const float* Win  = (const float*)d_in[2];  // [N,OBS]
    const float* Wout = (const float*)d_in[3];  // [A,N]
    float*       out  = (float*)d_out;          // [B,T,A]

    prep_kernel<<<1024, 256>>>(Wrec, Wout);
    dim3 g((BB * TT) / 128, NN / 64);
    ingemm_kernel<<<g, 256>>>(X, Win);
    lif_kernel<<<BB, 512>>>(out);
}

// round 6
// speedup vs baseline: 1.9724x; 1.9724x over previous
#include <cuda_runtime.h>
#include <cstdint>
#include <cmath>

#define BB   256
#define TT   1024
#define OBS  64
#define NN   512
#define AA   8
#define BETA 0.9f
#define V_TH 1.0f

#define BT      16                 // batch rows per block (= warps per block)
#define NT      64                 // neurons per block
#define NBG     (BB / BT)          // 16 batch groups
#define NNT     (NN / NT)          // 8 neuron tiles
#define GRID    (NBG * NNT)        // 128 blocks, all co-resident (1/SM)
#define THREADS 512

// Scratch: __device__ globals (runtime allocation is forbidden)
__device__ float    g_WT[NN * NN];               // W_T[j][i] = W_rec[i][j]
__device__ float    g_I[(size_t)BB * TT * NN];   // x @ W_in^T, precomputed
__device__ unsigned g_mask[2][BB][NN / 32];      // spike bitmasks, parity-buffered
__device__ float    g_part[2][BB][NNT][AA];      // output partial sums
__device__ unsigned g_bar_count;                 // monotone barrier counter
__device__ unsigned g_bar_flag;                  // barrier release flag

// ---------- prep: transpose W_rec, reset barrier state ----------
__global__ void prep_kernel(const float* __restrict__ Wrec)
{
    int idx = blockIdx.x * 256 + threadIdx.x;
    if (idx < NN * NN) {
        int i = idx >> 9, j = idx & (NN - 1);
        g_WT[j * NN + i] = Wrec[idx];
    }
    if (idx == 0) { g_bar_count = 0u; g_bar_flag = 0u; }
}

// ---------- input GEMM: g_I[r,i] = sum_k X[r,k] * Win[i,k]  (UNCHANGED, bitwise-load-bearing) ----------
__global__ void __launch_bounds__(256, 2) ingemm_kernel(const float* __restrict__ X,
                                                        const float* __restrict__ Win)
{
    __shared__ float As[128][OBS];
    __shared__ float Bs[OBS][64];
    const int row0 = blockIdx.x * 128;
    const int col0 = blockIdx.y * 64;
    const int tid  = threadIdx.x;

    #pragma unroll
    for (int l = tid; l < 128 * 16; l += 256) {
        int r = l >> 4, kq = l & 15;
        float4 v = reinterpret_cast<const float4*>(X + (size_t)(row0 + r) * OBS)[kq];
        *reinterpret_cast<float4*>(&As[r][kq * 4]) = v;
    }
    #pragma unroll
    for (int l = tid; l < 64 * 16; l += 256) {
        int i = l & 63, kq = l >> 6;
        float4 v = reinterpret_cast<const float4*>(Win + (size_t)(col0 + i) * OBS)[kq];
        Bs[kq * 4 + 0][i] = v.x;
        Bs[kq * 4 + 1][i] = v.y;
        Bs[kq * 4 + 2][i] = v.z;
        Bs[kq * 4 + 3][i] = v.w;
    }
    __syncthreads();

    const int tx = tid & 15, ty = tid >> 4;
    float acc[8][4];
    #pragma unroll
    for (int u = 0; u < 8; u++)
        #pragma unroll
        for (int c = 0; c < 4; c++) acc[u][c] = 0.f;

    #pragma unroll 8
    for (int k = 0; k < OBS; k++) {
        float4 b4 = *reinterpret_cast<const float4*>(&Bs[k][tx * 4]);
        #pragma unroll
        for (int u = 0; u < 8; u++) {
            float a = As[ty * 8 + u][k];
            acc[u][0] = __fmaf_rn(a, b4.x, acc[u][0]);
            acc[u][1] = __fmaf_rn(a, b4.y, acc[u][1]);
            acc[u][2] = __fmaf_rn(a, b4.z, acc[u][2]);
            acc[u][3] = __fmaf_rn(a, b4.w, acc[u][3]);
        }
    }
    #pragma unroll
    for (int u = 0; u < 8; u++) {
        size_t r = (size_t)(row0 + ty * 8 + u);
        float4 st = make_float4(acc[u][0], acc[u][1], acc[u][2], acc[u][3]);
        *reinterpret_cast<float4*>(&g_I[r * NN + col0 + tx * 4]) = st;
    }
}

// ---------- grid barrier: release/acquire, monotone counter (reset by prep) ----------
__device__ __forceinline__ void grid_barrier(unsigned target)
{
    __syncthreads();
    if (threadIdx.x == 0) {
        unsigned prev, one = 1u;
        asm volatile("atom.release.gpu.add.u32 %0, [%1], %2;"
                     : "=r"(prev) : "l"(&g_bar_count), "r"(one) : "memory");
        if (prev == target * GRID - 1u) {
            asm volatile("st.release.gpu.u32 [%0], %1;"
                         :: "l"(&g_bar_flag), "r"(target) : "memory");
        } else {
            unsigned f;
            do {
                asm volatile("ld.acquire.gpu.u32 %0, [%1];"
                             : "=r"(f) : "l"(&g_bar_flag) : "memory");
            } while (f < target);
        }
    }
    __syncthreads();
}

// ---------- persistent cooperative LIF: W slice stationary in SMEM ----------
// block = (batch group bg of 16 rows) x (neuron tile nt of 64 neurons)
// warp w -> batch row b0+w; lane owns neurons i0+lane and i0+32+lane.
// Bitwise state path identical to the passing kernel:
//   R via sequential __fadd_rn over spiking j (increasing), v' = fma(BETA,v,R)+I-s.
__global__ void __launch_bounds__(THREADS, 1) lif_kernel(float* __restrict__ out,
                                                         const float* __restrict__ Wout)
{
    extern __shared__ float smem[];
    float*          Ws     = smem;                                   // Ws[j*NT + il], 128KB
    unsigned short* s_list = (unsigned short*)(smem + NN * NT);      // [16][512], 16KB

    const int blk  = blockIdx.x;
    const int bg   = blk >> 3;         // 0..15
    const int nt   = blk & 7;          // 0..7
    const int b0   = bg * BT;
    const int i0   = nt * NT;
    const int tid  = threadIdx.x;
    const int warp = tid >> 5, lane = tid & 31;
    const int b    = b0 + warp;        // this warp's batch row

    // Load W slice: Ws[j][il] = g_WT[j*NN + i0 + il]  (coalesced 128B per warp)
    {
        const int jl = tid >> 6, il = tid & 63;
        for (int j = jl; j < NN; j += 8)
            Ws[j * NT + il] = g_WT[j * NN + i0 + il];
    }

    // Zero my words of the parity-0 mask buffer (covers all of g_mask[0])
    if (tid < BT * 2) {
        int r = tid >> 1, w = tid & 1;
        g_mask[0][b0 + r][nt * 2 + w] = 0u;
    }

    // Per-lane output weights for this tile
    float wo0[AA], wo1[AA];
    #pragma unroll
    for (int a = 0; a < AA; a++) {
        wo0[a] = Wout[a * NN + i0 + lane];
        wo1[a] = Wout[a * NN + i0 + 32 + lane];
    }

    float v0 = 0.f, v1 = 0.f;
    bool  sp0 = false, sp1 = false;

    grid_barrier(1);   // masks(par0) zeroed everywhere; smem W ready

    unsigned short* lst = s_list + warp * NN;
    const float*    wsl = Ws + lane;
    float*          orow = out + (size_t)b * TT * AA;

    for (int t = 0; t < TT; t++) {
        const int par = t & 1;

        // Finalize out(t-1): nt==0 blocks, fixed tile order (output path, tolerance-checked)
        if (t > 0 && nt == 0 && tid < BT * AA) {
            int r = tid >> 3, a = tid & 7;
            float s = 0.f;
            #pragma unroll
            for (int q = 0; q < NNT; q++) s += __ldcg(&g_part[par ^ 1][b0 + r][q][a]);
            out[((size_t)(b0 + r) * TT + (t - 1)) * AA + a] = (float)tanh((double)s);
        }

        // Read my row's 16 mask words (L2, parity slot t&1), decode to ordered list
        unsigned mw = (lane < 16) ? __ldcg(&g_mask[par][b][lane]) : 0u;
        int nsp = 0;
        #pragma unroll
        for (int w = 0; w < 16; w++) {
            unsigned m = __shfl_sync(0xffffffffu, mw, w);
            if ((m >> lane) & 1u)
                lst[nsp + __popc(m & ((1u << lane) - 1u))] = (unsigned short)(w * 32 + lane);
            nsp += __popc(m);
        }
        __syncwarp();

        // Sparse recurrent gather from SMEM: strict sequential adds, increasing j
        float R0 = 0.f, R1 = 0.f;
        int l = 0;
        for (; l + 4 <= nsp; l += 4) {
            int j0 = lst[l], j1 = lst[l + 1], j2 = lst[l + 2], j3 = lst[l + 3];
            float a0 = wsl[j0 * NT], c0 = wsl[j0 * NT + 32];
            float a1 = wsl[j1 * NT], c1 = wsl[j1 * NT + 32];
            float a2 = wsl[j2 * NT], c2 = wsl[j2 * NT + 32];
            float a3 = wsl[j3 * NT], c3 = wsl[j3 * NT + 32];
            R0 = __fadd_rn(R0, a0); R1 = __fadd_rn(R1, c0);
            R0 = __fadd_rn(R0, a1); R1 = __fadd_rn(R1, c1);
            R0 = __fadd_rn(R0, a2); R1 = __fadd_rn(R1, c2);
            R0 = __fadd_rn(R0, a3); R1 = __fadd_rn(R1, c3);
        }
        for (; l < nsp; l++) {
            int j = lst[l];
            R0 = __fadd_rn(R0, wsl[j * NT]);
            R1 = __fadd_rn(R1, wsl[j * NT + 32]);
        }

        // v' = (fma(BETA,v,R) + I) - V_TH*s   (exact passing-kernel ordering)
        const float* Ir = g_I + ((size_t)b * TT + t) * NN + i0;
        float acc0 = __fmaf_rn(BETA, v0, R0);
        acc0 = __fadd_rn(acc0, __ldg(Ir + lane));
        if (sp0) acc0 = __fadd_rn(acc0, -V_TH);
        v0 = acc0; sp0 = v0 > V_TH;

        float acc1 = __fmaf_rn(BETA, v1, R1);
        acc1 = __fadd_rn(acc1, __ldg(Ir + 32 + lane));
        if (sp1) acc1 = __fadd_rn(acc1, -V_TH);
        v1 = acc1; sp1 = v1 > V_TH;

        // Publish next-step spike words for this tile
        unsigned m0 = __ballot_sync(0xffffffffu, sp0);
        unsigned m1 = __ballot_sync(0xffffffffu, sp1);
        if (lane == 0) {
            g_mask[par ^ 1][b][nt * 2 + 0] = m0;
            g_mask[par ^ 1][b][nt * 2 + 1] = m1;
        }

        // Output partials for this tile: shuffle-reduce v*wo over 64 neurons
        float p[AA];
        #pragma unroll
        for (int a = 0; a < AA; a++) {
            p[a] = v0 * wo0[a] + v1 * wo1[a];
            #pragma unroll
            for (int off = 16; off > 0; off >>= 1)
                p[a] += __shfl_down_sync(0xffffffffu, p[a], off);
        }
        if (lane == 0) {
            #pragma unroll
            for (int a = 0; a < AA; a++) g_part[par][b][nt][a] = p[a];
        }

        grid_barrier((unsigned)(t + 2));
    }

    // Finalize out(TT-1)
    if (nt == 0 && tid < BT * AA) {
        int r = tid >> 3, a = tid & 7;
        float s = 0.f;
        #pragma unroll
        for (int q = 0; q < NNT; q++) s += __ldcg(&g_part[(TT - 1) & 1][b0 + r][q][a]);
        out[((size_t)(b0 + r) * TT + (TT - 1)) * AA + a] = (float)tanh((double)s);
    }
    (void)orow;
}

extern "C" void kernel_launch(void* const* d_in, const int* in_sizes, int n_in,
                              void* d_out, int out_size)
{
    const float* X    = (const float*)d_in[0];  // [B,T,OBS]
    const float* Wrec = (const float*)d_in[1];  // [N,N]
    const float* Win  = (const float*)d_in[2];  // [N,OBS]
    const float* Wout = (const float*)d_in[3];  // [A,N]
    float*       out  = (float*)d_out;          // [B,T,A]

    const int smem_bytes = NN * NT * 4 + BT * NN * 2;   // 128KB W + 16KB lists
    static bool attr_done = false;
    if (!attr_done) {
        cudaFuncSetAttribute(lif_kernel, cudaFuncAttributeMaxDynamicSharedMemorySize, smem_bytes);
        attr_done = true;
    }

    prep_kernel<<<1024, 256>>>(Wrec);
    dim3 g((BB * TT) / 128, NN / 64);
    ingemm_kernel<<<g, 256>>>(X, Win);
    lif_kernel<<<GRID, THREADS, smem_bytes>>>(out, Wout);
}